// round 5
// baseline (speedup 1.0000x reference)
#include <cuda_runtime.h>
#include <cstddef>

#define C_SEQ   2304
#define C_DIM   2048
#define C_ROWS  4608
#define C_FFN   8192
#define C_SCALE 0.08838834764831845f   // 1/sqrt(128)

typedef unsigned long long ull;

// ----------------------------------------------------------------- scratch
__device__ float g_t1[6144];
__device__ float g_t2[6144];
__device__ float g_norm[(size_t)C_ROWS * C_DIM];
__device__ float g_q [(size_t)C_ROWS * C_DIM];
__device__ float g_k [(size_t)C_ROWS * C_DIM];
__device__ float g_v [(size_t)C_ROWS * C_DIM];
__device__ float g_ao[(size_t)C_ROWS * C_DIM];
__device__ float g_tp[(size_t)C_ROWS * C_DIM];
__device__ float g_mid[(size_t)C_ROWS * C_FFN];

// ----------------------------------------------------------------- f32x2
__device__ __forceinline__ ull pack2(float lo, float hi) {
    ull r; asm("mov.b64 %0, {%1, %2};" : "=l"(r) : "f"(lo), "f"(hi)); return r;
}
__device__ __forceinline__ float2 unpack2(ull v) {
    float2 r; asm("mov.b64 {%0, %1}, %2;" : "=f"(r.x), "=f"(r.y) : "l"(v)); return r;
}
__device__ __forceinline__ void fma2(ull &d, ull a, ull b) {
    asm("fma.rn.f32x2 %0, %1, %2, %0;" : "+l"(d) : "l"(a), "l"(b));
}

// ----------------------------------------------------------------- temb -> t1/t2
__global__ __launch_bounds__(256) void temb_kernel(
    const float* __restrict__ temb,
    const float* __restrict__ lw1, const float* __restrict__ lb1,
    const float* __restrict__ lw2, const float* __restrict__ lb2,
    float* __restrict__ t1, float* __restrict__ t2)
{
    __shared__ float s[512];
    int tid = threadIdx.x;
    float a = temb[tid], b = temb[tid + 256];
    s[tid]       = a / (1.f + __expf(-a));
    s[tid + 256] = b / (1.f + __expf(-b));
    __syncthreads();
    const float* lw = blockIdx.y ? lw2 : lw1;
    const float* lb = blockIdx.y ? lb2 : lb1;
    float* t        = blockIdx.y ? t2  : t1;
    int j = blockIdx.x * 256 + tid;
    float acc = lb[j];
#pragma unroll 8
    for (int i = 0; i < 512; ++i) acc += s[i] * lw[(size_t)i * 6144 + j];
    t[j] = acc;
}

// ----------------------------------------------------------------- LN + modulation
__global__ __launch_bounds__(256) void ln_mod_kernel(
    const float* __restrict__ st, const float* __restrict__ t,
    const float* __restrict__ nw, const float* __restrict__ nb,
    float* __restrict__ dst)
{
    int row = blockIdx.x, tid = threadIdx.x;
    const float* x = st + (size_t)row * C_DIM;
    float4 v0 = *(const float4*)(x + tid * 8);
    float4 v1 = *(const float4*)(x + tid * 8 + 4);
    float xv[8] = {v0.x, v0.y, v0.z, v0.w, v1.x, v1.y, v1.z, v1.w};
    float s = 0.f, ss = 0.f;
#pragma unroll
    for (int e = 0; e < 8; ++e) { s += xv[e]; ss += xv[e] * xv[e]; }
#pragma unroll
    for (int o = 16; o > 0; o >>= 1) {
        s  += __shfl_xor_sync(0xffffffffu, s, o);
        ss += __shfl_xor_sync(0xffffffffu, ss, o);
    }
    __shared__ float rs[8], rss[8];
    if ((tid & 31) == 0) { rs[tid >> 5] = s; rss[tid >> 5] = ss; }
    __syncthreads();
    float tot = 0.f, tot2 = 0.f;
#pragma unroll
    for (int w = 0; w < 8; ++w) { tot += rs[w]; tot2 += rss[w]; }
    float mu   = tot * (1.f / 2048.f);
    float var  = tot2 * (1.f / 2048.f) - mu * mu;
    float rstd = rsqrtf(var + 1e-5f);
    float out[8];
#pragma unroll
    for (int e = 0; e < 8; ++e) {
        int c = tid * 8 + e;
        float xn = (xv[e] - mu) * rstd * nw[c] + nb[c];
        out[e] = xn * (1.f + t[2048 + c]) + t[c];
    }
    float* d = dst + (size_t)row * C_DIM + tid * 8;
    *(float4*)d       = make_float4(out[0], out[1], out[2], out[3]);
    *(float4*)(d + 4) = make_float4(out[4], out[5], out[6], out[7]);
}

// ----------------------------------------------------------------- GEMM (f32x2)
__device__ __forceinline__ float gelu_t(float x) {
    float x3 = x * x * x;
    return 0.5f * x * (1.f + tanhf(0.7978845608028654f * (x + 0.044715f * x3)));
}

__global__ __launch_bounds__(256, 2) void gemm_kernel(
    const float* __restrict__ A, const float* __restrict__ B,
    const float* __restrict__ bias, float* __restrict__ C,
    int M, int N, int K, int act)
{
    __shared__ float As[8][128];
    __shared__ float Bs[8][128];
    const int tid  = threadIdx.x;
    const int bm   = blockIdx.y << 7;
    const int bn   = blockIdx.x << 7;
    const int arow = tid >> 1;
    const int acol = (tid & 1) << 2;
    const int brow = tid >> 5;
    const int bcol = (tid & 31) << 2;
    const int rb   = (tid >> 4) << 3;
    const int cb   = (tid & 15) << 3;

    const float* Ap = A + (size_t)(bm + arow) * K + acol;
    const float* Bp = B + (size_t)brow * N + bn + bcol;

    ull acc[4][8];
#pragma unroll
    for (int p = 0; p < 4; ++p)
#pragma unroll
        for (int j = 0; j < 8; ++j) acc[p][j] = 0ull;

    float4 a4 = *(const float4*)Ap;
    float4 b4 = *(const float4*)Bp;
    const int nt = K >> 3;
    for (int tI = 0; tI < nt; ++tI) {
        As[acol + 0][arow] = a4.x;
        As[acol + 1][arow] = a4.y;
        As[acol + 2][arow] = a4.z;
        As[acol + 3][arow] = a4.w;
        *(float4*)&Bs[brow][bcol] = b4;
        __syncthreads();
        if (tI + 1 < nt) {
            a4 = *(const float4*)(Ap + (tI + 1) * 8);
            b4 = *(const float4*)(Bp + (size_t)(tI + 1) * 8 * N);
        }
#pragma unroll
        for (int k = 0; k < 8; ++k) {
            float4 af0 = *(const float4*)&As[k][rb];
            float4 af1 = *(const float4*)&As[k][rb + 4];
            float4 bf0 = *(const float4*)&Bs[k][cb];
            float4 bf1 = *(const float4*)&Bs[k][cb + 4];
            ull ap[4] = {pack2(af0.x, af0.y), pack2(af0.z, af0.w),
                         pack2(af1.x, af1.y), pack2(af1.z, af1.w)};
            ull bd[8] = {pack2(bf0.x, bf0.x), pack2(bf0.y, bf0.y),
                         pack2(bf0.z, bf0.z), pack2(bf0.w, bf0.w),
                         pack2(bf1.x, bf1.x), pack2(bf1.y, bf1.y),
                         pack2(bf1.z, bf1.z), pack2(bf1.w, bf1.w)};
#pragma unroll
            for (int p = 0; p < 4; ++p)
#pragma unroll
                for (int j = 0; j < 8; ++j)
                    fma2(acc[p][j], ap[p], bd[j]);
        }
        __syncthreads();
    }
#pragma unroll
    for (int p = 0; p < 4; ++p) {
        float o0[8], o1[8];
#pragma unroll
        for (int j = 0; j < 8; ++j) {
            float2 u = unpack2(acc[p][j]);
            float bz = bias[bn + cb + j];
            o0[j] = u.x + bz;
            o1[j] = u.y + bz;
        }
        if (act == 1) {
#pragma unroll
            for (int j = 0; j < 8; ++j) { o0[j] = gelu_t(o0[j]); o1[j] = gelu_t(o1[j]); }
        }
        size_t r0 = (size_t)(bm + rb + 2 * p) * N + bn + cb;
        *(float4*)&C[r0]         = make_float4(o0[0], o0[1], o0[2], o0[3]);
        *(float4*)&C[r0 + 4]     = make_float4(o0[4], o0[5], o0[6], o0[7]);
        *(float4*)&C[r0 + N]     = make_float4(o1[0], o1[1], o1[2], o1[3]);
        *(float4*)&C[r0 + N + 4] = make_float4(o1[4], o1[5], o1[6], o1[7]);
    }
}

// ----------------------------------------------------------------- RMSNorm + RoPE
__global__ __launch_bounds__(256) void rmsrope_kernel(
    float* __restrict__ Qm, float* __restrict__ Km,
    const float* __restrict__ nq, const float* __restrict__ nk,
    const float* __restrict__ cos_h, const float* __restrict__ sin_h,
    const float* __restrict__ cos_r, const float* __restrict__ sin_r)
{
    int row = blockIdx.x, tid = threadIdx.x;
    float* x = (blockIdx.y ? Km : Qm) + (size_t)row * C_DIM;
    const float* nw = blockIdx.y ? nk : nq;
    int isr = row >= C_SEQ;
    int pos = isr ? row - C_SEQ : row;
    const float* cp = (isr ? cos_r : cos_h) + (size_t)pos * 128;
    const float* sp = (isr ? sin_r : sin_h) + (size_t)pos * 128;
    float4 v0 = *(const float4*)(x + tid * 8);
    float4 v1 = *(const float4*)(x + tid * 8 + 4);
    float xv[8] = {v0.x, v0.y, v0.z, v0.w, v1.x, v1.y, v1.z, v1.w};
    float ss = 0.f;
#pragma unroll
    for (int e = 0; e < 8; ++e) ss += xv[e] * xv[e];
#pragma unroll
    for (int o = 16; o > 0; o >>= 1) ss += __shfl_xor_sync(0xffffffffu, ss, o);
    __shared__ float rss[8];
    if ((tid & 31) == 0) rss[tid >> 5] = ss;
    __syncthreads();
    float tot = 0.f;
#pragma unroll
    for (int w = 0; w < 8; ++w) tot += rss[w];
    float rstd = rsqrtf(tot * (1.f / 2048.f) + 1e-6f);
    float out[8];
#pragma unroll
    for (int p = 0; p < 4; ++p) {
        int ce = tid * 8 + 2 * p;
        int de = ce & 127;
        float x1 = xv[2 * p]     * rstd * nw[ce];
        float x2 = xv[2 * p + 1] * rstd * nw[ce + 1];
        float cv = cp[de], sv = sp[de + 1];
        out[2 * p]     = x1 * cv - x2 * sv;
        out[2 * p + 1] = x1 * sv + x2 * cv;
    }
    *(float4*)(x + tid * 8)     = make_float4(out[0], out[1], out[2], out[3]);
    *(float4*)(x + tid * 8 + 4) = make_float4(out[4], out[5], out[6], out[7]);
}

// ----------------------------------------------------------------- attention
__device__ __forceinline__ int combined_row(int fi, int j) {
    int hi = j / 48;
    int wi = j - hi * 48;
    int base = (wi < 24) ? 0 : C_SEQ;
    int ww   = (wi < 24) ? wi : wi - 24;
    return base + fi * 576 + hi * 24 + ww;
}

#define AT_STR 65
#define ATTN_SMEM ((128 * AT_STR * 2 + 64 * 128 + 64 * 66 + 192) * 4)

__global__ __launch_bounds__(256) void attn_kernel(
    const float* __restrict__ Q, const float* __restrict__ K,
    const float* __restrict__ V, float* __restrict__ O)
{
    extern __shared__ float sm[];
    float* Qt   = sm;                        // [128][65] d-major, pre-scaled
    float* Kt   = Qt + 128 * AT_STR;         // [128][65] d-major
    float* Vs   = Kt + 128 * AT_STR;         // [64][128]
    float* Sb   = Vs + 64 * 128;             // [64][66]
    float* mrow = Sb + 64 * 66;
    float* lrow = mrow + 64;
    float* arow = lrow + 64;

    const int tid  = threadIdx.x;
    const int fi   = blockIdx.y >> 4;
    const int coloff = (blockIdx.y & 15) * 128;
    const int q0   = blockIdx.x * 64;
    const int ty   = tid >> 4, tx = tid & 15;
    const int r0   = ty * 4, c0 = tx * 4, cv0 = tx * 8;

#pragma unroll
    for (int it = 0; it < 8; ++it) {
        int idx = tid + it * 256;
        int r = idx >> 5, d0 = (idx & 31) << 2;
        int grow = combined_row(fi, q0 + r);
        float4 qv = *(const float4*)&Q[(size_t)grow * C_DIM + coloff + d0];
        Qt[(d0 + 0) * AT_STR + r] = qv.x * C_SCALE;
        Qt[(d0 + 1) * AT_STR + r] = qv.y * C_SCALE;
        Qt[(d0 + 2) * AT_STR + r] = qv.z * C_SCALE;
        Qt[(d0 + 3) * AT_STR + r] = qv.w * C_SCALE;
    }
    if (tid < 64) { mrow[tid] = -1e30f; lrow[tid] = 0.f; }

    float acc[4][8];
#pragma unroll
    for (int i = 0; i < 4; ++i)
#pragma unroll
        for (int j = 0; j < 8; ++j) acc[i][j] = 0.f;

    for (int kc = 0; kc < 18; ++kc) {
        int k0 = kc * 64;
        __syncthreads();
#pragma unroll
        for (int it = 0; it < 8; ++it) {
            int idx = tid + it * 256;
            int r = idx >> 5, d0 = (idx & 31) << 2;
            int grow = combined_row(fi, k0 + r);
            float4 kv = *(const float4*)&K[(size_t)grow * C_DIM + coloff + d0];
            Kt[(d0 + 0) * AT_STR + r] = kv.x;
            Kt[(d0 + 1) * AT_STR + r] = kv.y;
            Kt[(d0 + 2) * AT_STR + r] = kv.z;
            Kt[(d0 + 3) * AT_STR + r] = kv.w;
        }
#pragma unroll
        for (int it = 0; it < 8; ++it) {
            int idx = tid + it * 256;
            int r = idx >> 5, c4 = (idx & 31) << 2;
            int grow = combined_row(fi, k0 + r);
            *(float4*)&Vs[r * 128 + c4] =
                *(const float4*)&V[(size_t)grow * C_DIM + coloff + c4];
        }
        __syncthreads();

        // S = Q K^T (scaled via Q)
        float s[4][4];
#pragma unroll
        for (int i = 0; i < 4; ++i)
#pragma unroll
            for (int j = 0; j < 4; ++j) s[i][j] = 0.f;
        for (int d = 0; d < 128; ++d) {
            const float* qr = &Qt[d * AT_STR + r0];
            const float* kr = &Kt[d * AT_STR + c0];
            float qa = qr[0], qb = qr[1], qc = qr[2], qd = qr[3];
            float ka = kr[0], kb = kr[1], kcv = kr[2], kd = kr[3];
            s[0][0] += qa * ka; s[0][1] += qa * kb; s[0][2] += qa * kcv; s[0][3] += qa * kd;
            s[1][0] += qb * ka; s[1][1] += qb * kb; s[1][2] += qb * kcv; s[1][3] += qb * kd;
            s[2][0] += qc * ka; s[2][1] += qc * kb; s[2][2] += qc * kcv; s[2][3] += qc * kd;
            s[3][0] += qd * ka; s[3][1] += qd * kb; s[3][2] += qd * kcv; s[3][3] += qd * kd;
        }
#pragma unroll
        for (int i = 0; i < 4; ++i)
#pragma unroll
            for (int j = 0; j < 4; ++j)
                Sb[(r0 + i) * 66 + c0 + j] = s[i][j];
        __syncthreads();

        // online softmax, one thread per row
        if (tid < 64) {
            float m = mrow[tid];
            float mx = m;
            float* sr = &Sb[tid * 66];
#pragma unroll 8
            for (int c = 0; c < 64; ++c) mx = fmaxf(mx, sr[c]);
            float fac = __expf(m - mx);
            float l = lrow[tid] * fac;
#pragma unroll 8
            for (int c = 0; c < 64; ++c) {
                float e = __expf(sr[c] - mx);
                sr[c] = e;
                l += e;
            }
            mrow[tid] = mx; lrow[tid] = l; arow[tid] = fac;
        }
        __syncthreads();

        float f0 = arow[r0], f1 = arow[r0 + 1], f2 = arow[r0 + 2], f3 = arow[r0 + 3];
#pragma unroll
        for (int j = 0; j < 8; ++j) {
            acc[0][j] *= f0; acc[1][j] *= f1; acc[2][j] *= f2; acc[3][j] *= f3;
        }
        // PV
        for (int c = 0; c < 64; ++c) {
            float p0 = Sb[(r0 + 0) * 66 + c];
            float p1 = Sb[(r0 + 1) * 66 + c];
            float p2 = Sb[(r0 + 2) * 66 + c];
            float p3 = Sb[(r0 + 3) * 66 + c];
            float4 va = *(const float4*)&Vs[c * 128 + cv0];
            float4 vb = *(const float4*)&Vs[c * 128 + cv0 + 4];
            float vv[8] = {va.x, va.y, va.z, va.w, vb.x, vb.y, vb.z, vb.w};
#pragma unroll
            for (int j = 0; j < 8; ++j) {
                acc[0][j] += p0 * vv[j];
                acc[1][j] += p1 * vv[j];
                acc[2][j] += p2 * vv[j];
                acc[3][j] += p3 * vv[j];
            }
        }
    }
    __syncthreads();
#pragma unroll
    for (int i = 0; i < 4; ++i) {
        float inv = 1.f / lrow[r0 + i];
        int grow = combined_row(fi, q0 + r0 + i);
        float* op = &O[(size_t)grow * C_DIM + coloff + cv0];
        *(float4*)op       = make_float4(acc[i][0] * inv, acc[i][1] * inv,
                                         acc[i][2] * inv, acc[i][3] * inv);
        *(float4*)(op + 4) = make_float4(acc[i][4] * inv, acc[i][5] * inv,
                                         acc[i][6] * inv, acc[i][7] * inv);
    }
}

// ----------------------------------------------------------------- residual gate
__global__ __launch_bounds__(256) void resid_kernel(
    float* __restrict__ st, const float* __restrict__ x, const float* __restrict__ t)
{
    size_t base = (size_t)blockIdx.x * C_DIM + threadIdx.x * 8;
    const float* g = t + 4096 + threadIdx.x * 8;
    float4 s0 = *(float4*)&st[base],     s1 = *(float4*)&st[base + 4];
    float4 x0 = *(const float4*)&x[base], x1 = *(const float4*)&x[base + 4];
    float4 g0 = *(const float4*)&g[0],   g1 = *(const float4*)&g[4];
    s0.x += g0.x * x0.x; s0.y += g0.y * x0.y; s0.z += g0.z * x0.z; s0.w += g0.w * x0.w;
    s1.x += g1.x * x1.x; s1.y += g1.y * x1.y; s1.z += g1.z * x1.z; s1.w += g1.w * x1.w;
    *(float4*)&st[base]     = s0;
    *(float4*)&st[base + 4] = s1;
}

// ----------------------------------------------------------------- launch
extern "C" void kernel_launch(void* const* d_in, const int* in_sizes, int n_in,
                              void* d_out, int out_size)
{
    const float* temb  = (const float*)d_in[2];
    const float* cos_h = (const float*)d_in[3];
    const float* sin_h = (const float*)d_in[4];
    const float* cos_r = (const float*)d_in[5];
    const float* sin_r = (const float*)d_in[6];
    const float* l1lw = (const float*)d_in[7],  *l1lb = (const float*)d_in[8];
    const float* l1nw = (const float*)d_in[9],  *l1nb = (const float*)d_in[10];
    const float* l2lw = (const float*)d_in[11], *l2lb = (const float*)d_in[12];
    const float* l2nw = (const float*)d_in[13], *l2nb = (const float*)d_in[14];
    const float* wq = (const float*)d_in[15], *bq = (const float*)d_in[16];
    const float* wk = (const float*)d_in[17], *bk = (const float*)d_in[18];
    const float* wv = (const float*)d_in[19], *bv = (const float*)d_in[20];
    const float* nqw = (const float*)d_in[21], *nkw = (const float*)d_in[22];
    const float* wo = (const float*)d_in[23], *bo = (const float*)d_in[24];
    const float* fw1 = (const float*)d_in[25], *fb1 = (const float*)d_in[26];
    const float* fw2 = (const float*)d_in[27], *fb2 = (const float*)d_in[28];
    float* st = (float*)d_out;

    float *t1, *t2, *nrm, *q, *k, *v, *ao, *tp, *mid;
    cudaGetSymbolAddress((void**)&t1,  g_t1);
    cudaGetSymbolAddress((void**)&t2,  g_t2);
    cudaGetSymbolAddress((void**)&nrm, g_norm);
    cudaGetSymbolAddress((void**)&q,   g_q);
    cudaGetSymbolAddress((void**)&k,   g_k);
    cudaGetSymbolAddress((void**)&v,   g_v);
    cudaGetSymbolAddress((void**)&ao,  g_ao);
    cudaGetSymbolAddress((void**)&tp,  g_tp);
    cudaGetSymbolAddress((void**)&mid, g_mid);

    size_t half = (size_t)C_SEQ * C_DIM * sizeof(float);
    cudaMemcpyAsync(st, d_in[0], half, cudaMemcpyDeviceToDevice, 0);
    cudaMemcpyAsync(st + (size_t)C_SEQ * C_DIM, d_in[1], half, cudaMemcpyDeviceToDevice, 0);

    cudaFuncSetAttribute(attn_kernel, cudaFuncAttributeMaxDynamicSharedMemorySize, ATTN_SMEM);

    temb_kernel<<<dim3(24, 2), 256>>>(temb, l1lw, l1lb, l2lw, l2lb, t1, t2);
    ln_mod_kernel<<<C_ROWS, 256>>>(st, t1, l1nw, l1nb, nrm);
    gemm_kernel<<<dim3(16, 36), 256>>>(nrm, wq, bq, q, C_ROWS, C_DIM, C_DIM, 0);
    gemm_kernel<<<dim3(16, 36), 256>>>(nrm, wk, bk, k, C_ROWS, C_DIM, C_DIM, 0);
    gemm_kernel<<<dim3(16, 36), 256>>>(nrm, wv, bv, v, C_ROWS, C_DIM, C_DIM, 0);
    rmsrope_kernel<<<dim3(C_ROWS, 2), 256>>>(q, k, nqw, nkw, cos_h, sin_h, cos_r, sin_r);
    attn_kernel<<<dim3(18, 64), 256, ATTN_SMEM>>>(q, k, v, ao);
    gemm_kernel<<<dim3(16, 36), 256>>>(ao, wo, bo, tp, C_ROWS, C_DIM, C_DIM, 0);
    resid_kernel<<<C_ROWS, 256>>>(st, tp, t1);
    ln_mod_kernel<<<C_ROWS, 256>>>(st, t2, l2nw, l2nb, nrm);
    gemm_kernel<<<dim3(64, 36), 256>>>(nrm, fw1, fb1, mid, C_ROWS, C_FFN, C_DIM, 1);
    gemm_kernel<<<dim3(16, 36), 256>>>(mid, fw2, fb2, tp, C_ROWS, C_DIM, C_FFN, 0);
    resid_kernel<<<C_ROWS, 256>>>(st, tp, t2);
}

// round 6
// speedup vs baseline: 1.0016x; 1.0016x over previous
#include <cuda_runtime.h>
#include <cstddef>

#define C_SEQ   2304
#define C_DIM   2048
#define C_ROWS  4608
#define C_FFN   8192
#define C_SCALE 0.08838834764831845f   // 1/sqrt(128)

typedef unsigned long long ull;

// ----------------------------------------------------------------- scratch
__device__ float g_t1[6144];
__device__ float g_t2[6144];
__device__ float g_norm[(size_t)C_ROWS * C_DIM];
__device__ float g_q [(size_t)C_ROWS * C_DIM];
__device__ float g_k [(size_t)C_ROWS * C_DIM];
__device__ float g_v [(size_t)C_ROWS * C_DIM];
__device__ float g_ao[(size_t)C_ROWS * C_DIM];
__device__ float g_tp[(size_t)C_ROWS * C_DIM];
__device__ float g_mid[(size_t)C_ROWS * C_FFN];

// ----------------------------------------------------------------- f32x2
__device__ __forceinline__ ull pack2(float lo, float hi) {
    ull r; asm("mov.b64 %0, {%1, %2};" : "=l"(r) : "f"(lo), "f"(hi)); return r;
}
__device__ __forceinline__ float2 unpack2(ull v) {
    float2 r; asm("mov.b64 {%0, %1}, %2;" : "=f"(r.x), "=f"(r.y) : "l"(v)); return r;
}
__device__ __forceinline__ void fma2(ull &d, ull a, ull b) {
    asm("fma.rn.f32x2 %0, %1, %2, %0;" : "+l"(d) : "l"(a), "l"(b));
}

// ----------------------------------------------------------------- temb -> t1/t2
__global__ __launch_bounds__(256) void temb_kernel(
    const float* __restrict__ temb,
    const float* __restrict__ lw1, const float* __restrict__ lb1,
    const float* __restrict__ lw2, const float* __restrict__ lb2,
    float* __restrict__ t1, float* __restrict__ t2)
{
    __shared__ float s[512];
    int tid = threadIdx.x;
    float a = temb[tid], b = temb[tid + 256];
    s[tid]       = a / (1.f + __expf(-a));
    s[tid + 256] = b / (1.f + __expf(-b));
    __syncthreads();
    const float* lw = blockIdx.y ? lw2 : lw1;
    const float* lb = blockIdx.y ? lb2 : lb1;
    float* t        = blockIdx.y ? t2  : t1;
    int j = blockIdx.x * 256 + tid;
    float acc = lb[j];
#pragma unroll 8
    for (int i = 0; i < 512; ++i) acc += s[i] * lw[(size_t)i * 6144 + j];
    t[j] = acc;
}

// ----------------------------------------------------------------- LN + modulation
__global__ __launch_bounds__(256) void ln_mod_kernel(
    const float* __restrict__ st, const float* __restrict__ t,
    const float* __restrict__ nw, const float* __restrict__ nb,
    float* __restrict__ dst)
{
    int row = blockIdx.x, tid = threadIdx.x;
    const float* x = st + (size_t)row * C_DIM;
    float4 v0 = *(const float4*)(x + tid * 8);
    float4 v1 = *(const float4*)(x + tid * 8 + 4);
    float xv[8] = {v0.x, v0.y, v0.z, v0.w, v1.x, v1.y, v1.z, v1.w};
    float s = 0.f, ss = 0.f;
#pragma unroll
    for (int e = 0; e < 8; ++e) { s += xv[e]; ss += xv[e] * xv[e]; }
#pragma unroll
    for (int o = 16; o > 0; o >>= 1) {
        s  += __shfl_xor_sync(0xffffffffu, s, o);
        ss += __shfl_xor_sync(0xffffffffu, ss, o);
    }
    __shared__ float rs[8], rss[8];
    if ((tid & 31) == 0) { rs[tid >> 5] = s; rss[tid >> 5] = ss; }
    __syncthreads();
    float tot = 0.f, tot2 = 0.f;
#pragma unroll
    for (int w = 0; w < 8; ++w) { tot += rs[w]; tot2 += rss[w]; }
    float mu   = tot * (1.f / 2048.f);
    float var  = tot2 * (1.f / 2048.f) - mu * mu;
    float rstd = rsqrtf(var + 1e-5f);
    float out[8];
#pragma unroll
    for (int e = 0; e < 8; ++e) {
        int c = tid * 8 + e;
        float xn = (xv[e] - mu) * rstd * nw[c] + nb[c];
        out[e] = xn * (1.f + t[2048 + c]) + t[c];
    }
    float* d = dst + (size_t)row * C_DIM + tid * 8;
    *(float4*)d       = make_float4(out[0], out[1], out[2], out[3]);
    *(float4*)(d + 4) = make_float4(out[4], out[5], out[6], out[7]);
}

// ----------------------------------------------------------------- GEMM (f32x2)
__device__ __forceinline__ float gelu_t(float x) {
    float x3 = x * x * x;
    return 0.5f * x * (1.f + tanhf(0.7978845608028654f * (x + 0.044715f * x3)));
}

__global__ __launch_bounds__(256, 2) void gemm_kernel(
    const float* __restrict__ A, const float* __restrict__ B,
    const float* __restrict__ bias, float* __restrict__ C,
    int M, int N, int K, int act)
{
    __shared__ float As[8][128];
    __shared__ float Bs[8][128];
    const int tid  = threadIdx.x;
    const int bm   = blockIdx.y << 7;
    const int bn   = blockIdx.x << 7;
    const int arow = tid >> 1;
    const int acol = (tid & 1) << 2;
    const int brow = tid >> 5;
    const int bcol = (tid & 31) << 2;
    const int rb   = (tid >> 4) << 3;
    const int cb   = (tid & 15) << 3;

    const float* Ap = A + (size_t)(bm + arow) * K + acol;
    const float* Bp = B + (size_t)brow * N + bn + bcol;

    ull acc[4][8];
#pragma unroll
    for (int p = 0; p < 4; ++p)
#pragma unroll
        for (int j = 0; j < 8; ++j) acc[p][j] = 0ull;

    float4 a4 = *(const float4*)Ap;
    float4 b4 = *(const float4*)Bp;
    const int nt = K >> 3;
    for (int tI = 0; tI < nt; ++tI) {
        As[acol + 0][arow] = a4.x;
        As[acol + 1][arow] = a4.y;
        As[acol + 2][arow] = a4.z;
        As[acol + 3][arow] = a4.w;
        *(float4*)&Bs[brow][bcol] = b4;
        __syncthreads();
        if (tI + 1 < nt) {
            a4 = *(const float4*)(Ap + (tI + 1) * 8);
            b4 = *(const float4*)(Bp + (size_t)(tI + 1) * 8 * N);
        }
#pragma unroll
        for (int k = 0; k < 8; ++k) {
            float4 af0 = *(const float4*)&As[k][rb];
            float4 af1 = *(const float4*)&As[k][rb + 4];
            float4 bf0 = *(const float4*)&Bs[k][cb];
            float4 bf1 = *(const float4*)&Bs[k][cb + 4];
            ull ap[4] = {pack2(af0.x, af0.y), pack2(af0.z, af0.w),
                         pack2(af1.x, af1.y), pack2(af1.z, af1.w)};
            ull bd[8] = {pack2(bf0.x, bf0.x), pack2(bf0.y, bf0.y),
                         pack2(bf0.z, bf0.z), pack2(bf0.w, bf0.w),
                         pack2(bf1.x, bf1.x), pack2(bf1.y, bf1.y),
                         pack2(bf1.z, bf1.z), pack2(bf1.w, bf1.w)};
#pragma unroll
            for (int p = 0; p < 4; ++p)
#pragma unroll
                for (int j = 0; j < 8; ++j)
                    fma2(acc[p][j], ap[p], bd[j]);
        }
        __syncthreads();
    }
#pragma unroll
    for (int p = 0; p < 4; ++p) {
        float o0[8], o1[8];
#pragma unroll
        for (int j = 0; j < 8; ++j) {
            float2 u = unpack2(acc[p][j]);
            float bz = bias[bn + cb + j];
            o0[j] = u.x + bz;
            o1[j] = u.y + bz;
        }
        if (act == 1) {
#pragma unroll
            for (int j = 0; j < 8; ++j) { o0[j] = gelu_t(o0[j]); o1[j] = gelu_t(o1[j]); }
        }
        size_t r0 = (size_t)(bm + rb + 2 * p) * N + bn + cb;
        *(float4*)&C[r0]         = make_float4(o0[0], o0[1], o0[2], o0[3]);
        *(float4*)&C[r0 + 4]     = make_float4(o0[4], o0[5], o0[6], o0[7]);
        *(float4*)&C[r0 + N]     = make_float4(o1[0], o1[1], o1[2], o1[3]);
        *(float4*)&C[r0 + N + 4] = make_float4(o1[4], o1[5], o1[6], o1[7]);
    }
}

// ----------------------------------------------------------------- RMSNorm + RoPE
__global__ __launch_bounds__(256) void rmsrope_kernel(
    float* __restrict__ Qm, float* __restrict__ Km,
    const float* __restrict__ nq, const float* __restrict__ nk,
    const float* __restrict__ cos_h, const float* __restrict__ sin_h,
    const float* __restrict__ cos_r, const float* __restrict__ sin_r)
{
    int row = blockIdx.x, tid = threadIdx.x;
    float* x = (blockIdx.y ? Km : Qm) + (size_t)row * C_DIM;
    const float* nw = blockIdx.y ? nk : nq;
    int isr = row >= C_SEQ;
    int pos = isr ? row - C_SEQ : row;
    const float* cp = (isr ? cos_r : cos_h) + (size_t)pos * 128;
    const float* sp = (isr ? sin_r : sin_h) + (size_t)pos * 128;
    float4 v0 = *(const float4*)(x + tid * 8);
    float4 v1 = *(const float4*)(x + tid * 8 + 4);
    float xv[8] = {v0.x, v0.y, v0.z, v0.w, v1.x, v1.y, v1.z, v1.w};
    float ss = 0.f;
#pragma unroll
    for (int e = 0; e < 8; ++e) ss += xv[e] * xv[e];
#pragma unroll
    for (int o = 16; o > 0; o >>= 1) ss += __shfl_xor_sync(0xffffffffu, ss, o);
    __shared__ float rss[8];
    if ((tid & 31) == 0) rss[tid >> 5] = ss;
    __syncthreads();
    float tot = 0.f;
#pragma unroll
    for (int w = 0; w < 8; ++w) tot += rss[w];
    float rstd = rsqrtf(tot * (1.f / 2048.f) + 1e-6f);
    float out[8];
#pragma unroll
    for (int p = 0; p < 4; ++p) {
        int ce = tid * 8 + 2 * p;
        int de = ce & 127;
        float x1 = xv[2 * p]     * rstd * nw[ce];
        float x2 = xv[2 * p + 1] * rstd * nw[ce + 1];
        float cv = cp[de], sv = sp[de + 1];
        out[2 * p]     = x1 * cv - x2 * sv;
        out[2 * p + 1] = x1 * sv + x2 * cv;
    }
    *(float4*)(x + tid * 8)     = make_float4(out[0], out[1], out[2], out[3]);
    *(float4*)(x + tid * 8 + 4) = make_float4(out[4], out[5], out[6], out[7]);
}

// ----------------------------------------------------------------- attention
__device__ __forceinline__ int combined_row(int fi, int j) {
    int hi = j / 48;
    int wi = j - hi * 48;
    int base = (wi < 24) ? 0 : C_SEQ;
    int ww   = (wi < 24) ? wi : wi - 24;
    return base + fi * 576 + hi * 24 + ww;
}

#define AT_STR 65
#define ATTN_SMEM ((128 * AT_STR * 2 + 64 * 128 + 64 * 66 + 192) * 4)

__global__ __launch_bounds__(256) void attn_kernel(
    const float* __restrict__ Q, const float* __restrict__ K,
    const float* __restrict__ V, float* __restrict__ O)
{
    extern __shared__ float sm[];
    float* Qt   = sm;                        // [128][65] d-major, pre-scaled
    float* Kt   = Qt + 128 * AT_STR;         // [128][65] d-major
    float* Vs   = Kt + 128 * AT_STR;         // [64][128]
    float* Sb   = Vs + 64 * 128;             // [64][66]
    float* mrow = Sb + 64 * 66;
    float* lrow = mrow + 64;
    float* arow = lrow + 64;

    const int tid  = threadIdx.x;
    const int fi   = blockIdx.y >> 4;
    const int coloff = (blockIdx.y & 15) * 128;
    const int q0   = blockIdx.x * 64;
    const int ty   = tid >> 4, tx = tid & 15;
    const int r0   = ty * 4, c0 = tx * 4, cv0 = tx * 8;

#pragma unroll
    for (int it = 0; it < 8; ++it) {
        int idx = tid + it * 256;
        int r = idx >> 5, d0 = (idx & 31) << 2;
        int grow = combined_row(fi, q0 + r);
        float4 qv = *(const float4*)&Q[(size_t)grow * C_DIM + coloff + d0];
        Qt[(d0 + 0) * AT_STR + r] = qv.x * C_SCALE;
        Qt[(d0 + 1) * AT_STR + r] = qv.y * C_SCALE;
        Qt[(d0 + 2) * AT_STR + r] = qv.z * C_SCALE;
        Qt[(d0 + 3) * AT_STR + r] = qv.w * C_SCALE;
    }
    if (tid < 64) { mrow[tid] = -1e30f; lrow[tid] = 0.f; }

    float acc[4][8];
#pragma unroll
    for (int i = 0; i < 4; ++i)
#pragma unroll
        for (int j = 0; j < 8; ++j) acc[i][j] = 0.f;

    for (int kc = 0; kc < 18; ++kc) {
        int k0 = kc * 64;
        __syncthreads();
#pragma unroll
        for (int it = 0; it < 8; ++it) {
            int idx = tid + it * 256;
            int r = idx >> 5, d0 = (idx & 31) << 2;
            int grow = combined_row(fi, k0 + r);
            float4 kv = *(const float4*)&K[(size_t)grow * C_DIM + coloff + d0];
            Kt[(d0 + 0) * AT_STR + r] = kv.x;
            Kt[(d0 + 1) * AT_STR + r] = kv.y;
            Kt[(d0 + 2) * AT_STR + r] = kv.z;
            Kt[(d0 + 3) * AT_STR + r] = kv.w;
        }
#pragma unroll
        for (int it = 0; it < 8; ++it) {
            int idx = tid + it * 256;
            int r = idx >> 5, c4 = (idx & 31) << 2;
            int grow = combined_row(fi, k0 + r);
            *(float4*)&Vs[r * 128 + c4] =
                *(const float4*)&V[(size_t)grow * C_DIM + coloff + c4];
        }
        __syncthreads();

        // S = Q K^T (scaled via Q)
        float s[4][4];
#pragma unroll
        for (int i = 0; i < 4; ++i)
#pragma unroll
            for (int j = 0; j < 4; ++j) s[i][j] = 0.f;
        for (int d = 0; d < 128; ++d) {
            const float* qr = &Qt[d * AT_STR + r0];
            const float* kr = &Kt[d * AT_STR + c0];
            float qa = qr[0], qb = qr[1], qc = qr[2], qd = qr[3];
            float ka = kr[0], kb = kr[1], kcv = kr[2], kd = kr[3];
            s[0][0] += qa * ka; s[0][1] += qa * kb; s[0][2] += qa * kcv; s[0][3] += qa * kd;
            s[1][0] += qb * ka; s[1][1] += qb * kb; s[1][2] += qb * kcv; s[1][3] += qb * kd;
            s[2][0] += qc * ka; s[2][1] += qc * kb; s[2][2] += qc * kcv; s[2][3] += qc * kd;
            s[3][0] += qd * ka; s[3][1] += qd * kb; s[3][2] += qd * kcv; s[3][3] += qd * kd;
        }
#pragma unroll
        for (int i = 0; i < 4; ++i)
#pragma unroll
            for (int j = 0; j < 4; ++j)
                Sb[(r0 + i) * 66 + c0 + j] = s[i][j];
        __syncthreads();

        // online softmax, one thread per row
        if (tid < 64) {
            float m = mrow[tid];
            float mx = m;
            float* sr = &Sb[tid * 66];
#pragma unroll 8
            for (int c = 0; c < 64; ++c) mx = fmaxf(mx, sr[c]);
            float fac = __expf(m - mx);
            float l = lrow[tid] * fac;
#pragma unroll 8
            for (int c = 0; c < 64; ++c) {
                float e = __expf(sr[c] - mx);
                sr[c] = e;
                l += e;
            }
            mrow[tid] = mx; lrow[tid] = l; arow[tid] = fac;
        }
        __syncthreads();

        float f0 = arow[r0], f1 = arow[r0 + 1], f2 = arow[r0 + 2], f3 = arow[r0 + 3];
#pragma unroll
        for (int j = 0; j < 8; ++j) {
            acc[0][j] *= f0; acc[1][j] *= f1; acc[2][j] *= f2; acc[3][j] *= f3;
        }
        // PV
        for (int c = 0; c < 64; ++c) {
            float p0 = Sb[(r0 + 0) * 66 + c];
            float p1 = Sb[(r0 + 1) * 66 + c];
            float p2 = Sb[(r0 + 2) * 66 + c];
            float p3 = Sb[(r0 + 3) * 66 + c];
            float4 va = *(const float4*)&Vs[c * 128 + cv0];
            float4 vb = *(const float4*)&Vs[c * 128 + cv0 + 4];
            float vv[8] = {va.x, va.y, va.z, va.w, vb.x, vb.y, vb.z, vb.w};
#pragma unroll
            for (int j = 0; j < 8; ++j) {
                acc[0][j] += p0 * vv[j];
                acc[1][j] += p1 * vv[j];
                acc[2][j] += p2 * vv[j];
                acc[3][j] += p3 * vv[j];
            }
        }
    }
    __syncthreads();
#pragma unroll
    for (int i = 0; i < 4; ++i) {
        float inv = 1.f / lrow[r0 + i];
        int grow = combined_row(fi, q0 + r0 + i);
        float* op = &O[(size_t)grow * C_DIM + coloff + cv0];
        *(float4*)op       = make_float4(acc[i][0] * inv, acc[i][1] * inv,
                                         acc[i][2] * inv, acc[i][3] * inv);
        *(float4*)(op + 4) = make_float4(acc[i][4] * inv, acc[i][5] * inv,
                                         acc[i][6] * inv, acc[i][7] * inv);
    }
}

// ----------------------------------------------------------------- residual gate
__global__ __launch_bounds__(256) void resid_kernel(
    float* __restrict__ st, const float* __restrict__ x, const float* __restrict__ t)
{
    size_t base = (size_t)blockIdx.x * C_DIM + threadIdx.x * 8;
    const float* g = t + 4096 + threadIdx.x * 8;
    float4 s0 = *(float4*)&st[base],     s1 = *(float4*)&st[base + 4];
    float4 x0 = *(const float4*)&x[base], x1 = *(const float4*)&x[base + 4];
    float4 g0 = *(const float4*)&g[0],   g1 = *(const float4*)&g[4];
    s0.x += g0.x * x0.x; s0.y += g0.y * x0.y; s0.z += g0.z * x0.z; s0.w += g0.w * x0.w;
    s1.x += g1.x * x1.x; s1.y += g1.y * x1.y; s1.z += g1.z * x1.z; s1.w += g1.w * x1.w;
    *(float4*)&st[base]     = s0;
    *(float4*)&st[base + 4] = s1;
}

// ----------------------------------------------------------------- launch
extern "C" void kernel_launch(void* const* d_in, const int* in_sizes, int n_in,
                              void* d_out, int out_size)
{
    const float* temb  = (const float*)d_in[2];
    const float* cos_h = (const float*)d_in[3];
    const float* sin_h = (const float*)d_in[4];
    const float* cos_r = (const float*)d_in[5];
    const float* sin_r = (const float*)d_in[6];
    const float* l1lw = (const float*)d_in[7],  *l1lb = (const float*)d_in[8];
    const float* l1nw = (const float*)d_in[9],  *l1nb = (const float*)d_in[10];
    const float* l2lw = (const float*)d_in[11], *l2lb = (const float*)d_in[12];
    const float* l2nw = (const float*)d_in[13], *l2nb = (const float*)d_in[14];
    const float* wq = (const float*)d_in[15], *bq = (const float*)d_in[16];
    const float* wk = (const float*)d_in[17], *bk = (const float*)d_in[18];
    const float* wv = (const float*)d_in[19], *bv = (const float*)d_in[20];
    const float* nqw = (const float*)d_in[21], *nkw = (const float*)d_in[22];
    const float* wo = (const float*)d_in[23], *bo = (const float*)d_in[24];
    const float* fw1 = (const float*)d_in[25], *fb1 = (const float*)d_in[26];
    const float* fw2 = (const float*)d_in[27], *fb2 = (const float*)d_in[28];
    float* st = (float*)d_out;

    float *t1, *t2, *nrm, *q, *k, *v, *ao, *tp, *mid;
    cudaGetSymbolAddress((void**)&t1,  g_t1);
    cudaGetSymbolAddress((void**)&t2,  g_t2);
    cudaGetSymbolAddress((void**)&nrm, g_norm);
    cudaGetSymbolAddress((void**)&q,   g_q);
    cudaGetSymbolAddress((void**)&k,   g_k);
    cudaGetSymbolAddress((void**)&v,   g_v);
    cudaGetSymbolAddress((void**)&ao,  g_ao);
    cudaGetSymbolAddress((void**)&tp,  g_tp);
    cudaGetSymbolAddress((void**)&mid, g_mid);

    size_t half = (size_t)C_SEQ * C_DIM * sizeof(float);
    cudaMemcpyAsync(st, d_in[0], half, cudaMemcpyDeviceToDevice, 0);
    cudaMemcpyAsync(st + (size_t)C_SEQ * C_DIM, d_in[1], half, cudaMemcpyDeviceToDevice, 0);

    cudaFuncSetAttribute(attn_kernel, cudaFuncAttributeMaxDynamicSharedMemorySize, ATTN_SMEM);

    temb_kernel<<<dim3(24, 2), 256>>>(temb, l1lw, l1lb, l2lw, l2lb, t1, t2);
    ln_mod_kernel<<<C_ROWS, 256>>>(st, t1, l1nw, l1nb, nrm);
    gemm_kernel<<<dim3(16, 36), 256>>>(nrm, wq, bq, q, C_ROWS, C_DIM, C_DIM, 0);
    gemm_kernel<<<dim3(16, 36), 256>>>(nrm, wk, bk, k, C_ROWS, C_DIM, C_DIM, 0);
    gemm_kernel<<<dim3(16, 36), 256>>>(nrm, wv, bv, v, C_ROWS, C_DIM, C_DIM, 0);
    rmsrope_kernel<<<dim3(C_ROWS, 2), 256>>>(q, k, nqw, nkw, cos_h, sin_h, cos_r, sin_r);
    attn_kernel<<<dim3(18, 64), 256, ATTN_SMEM>>>(q, k, v, ao);
    gemm_kernel<<<dim3(16, 36), 256>>>(ao, wo, bo, tp, C_ROWS, C_DIM, C_DIM, 0);
    resid_kernel<<<C_ROWS, 256>>>(st, tp, t1);
    ln_mod_kernel<<<C_ROWS, 256>>>(st, t2, l2nw, l2nb, nrm);
    gemm_kernel<<<dim3(64, 36), 256>>>(nrm, fw1, fb1, mid, C_ROWS, C_FFN, C_DIM, 1);
    gemm_kernel<<<dim3(16, 36), 256>>>(mid, fw2, fb2, tp, C_ROWS, C_DIM, C_FFN, 0);
    resid_kernel<<<C_ROWS, 256>>>(st, tp, t2);
}